// round 3
// baseline (speedup 1.0000x reference)
#include <cuda_runtime.h>
#include <cstdint>
#include <math.h>

typedef unsigned int u32;
typedef unsigned long long u64;

#define BB 128
#define HH 512
#define WW 512
#define HWL 262144      // 512*512
#define NBUK 4096
#define CAP 4096
#define NSEEDS 1000

// ---------------- device scratch (no allocation allowed) ----------------
__device__ u32 g_hist256[BB][256];
__device__ u32 g_histBG[BB][NBUK];
__device__ u32 g_histF[BB][NBUK];
__device__ u32 g_histG[BB][NBUK];
__device__ u32 g_cntBG[BB], g_cntF[BB], g_cntG[BB];
__device__ u64 g_bufBG[BB][CAP];
__device__ u64 g_bufF[BB][CAP];
__device__ u64 g_bufG[BB][CAP];
__device__ float g_th[BB];
__device__ int g_nbg[BB], g_cbg[BB], g_rbg[BB];
__device__ u64 g_KbgSel[BB];
__device__ int g_cF[BB], g_rF[BB], g_cG[BB], g_rG[BB];
__device__ uint2 g_kf[BB], g_kb[BB];
__device__ unsigned char g_tmpH[(size_t)BB * HWL];   // H-eroded, then reused as elig flags
__device__ unsigned char g_erod[(size_t)BB * HWL];
__device__ __align__(4) unsigned char g_mask[(size_t)BB * HWL];
__device__ u32 g_fbits[(size_t)BB * HWL];
__device__ u32 g_bbits[(size_t)BB * HWL];

// ---------------- threefry-2x32 (verified vs Random123 test vector) ----------------
__device__ __forceinline__ u32 rotl32(u32 x, int d) { return (x << d) | (x >> (32 - d)); }

__device__ __forceinline__ void tf2x32(u32 k0, u32 k1, u32 x0, u32 x1, u32& o0, u32& o1) {
    u32 ks0 = k0, ks1 = k1, ks2 = k0 ^ k1 ^ 0x1BD11BDAu;
    x0 += ks0; x1 += ks1;
    x0 += x1; x1 = rotl32(x1, 13); x1 ^= x0;
    x0 += x1; x1 = rotl32(x1, 15); x1 ^= x0;
    x0 += x1; x1 = rotl32(x1, 26); x1 ^= x0;
    x0 += x1; x1 = rotl32(x1,  6); x1 ^= x0;
    x0 += ks1; x1 += ks2 + 1u;
    x0 += x1; x1 = rotl32(x1, 17); x1 ^= x0;
    x0 += x1; x1 = rotl32(x1, 29); x1 ^= x0;
    x0 += x1; x1 = rotl32(x1, 16); x1 ^= x0;
    x0 += x1; x1 = rotl32(x1, 24); x1 ^= x0;
    x0 += ks2; x1 += ks0 + 2u;
    x0 += x1; x1 = rotl32(x1, 13); x1 ^= x0;
    x0 += x1; x1 = rotl32(x1, 15); x1 ^= x0;
    x0 += x1; x1 = rotl32(x1, 26); x1 ^= x0;
    x0 += x1; x1 = rotl32(x1,  6); x1 ^= x0;
    x0 += ks0; x1 += ks1 + 3u;
    x0 += x1; x1 = rotl32(x1, 17); x1 ^= x0;
    x0 += x1; x1 = rotl32(x1, 29); x1 ^= x0;
    x0 += x1; x1 = rotl32(x1, 16); x1 ^= x0;
    x0 += x1; x1 = rotl32(x1, 24); x1 ^= x0;
    x0 += ks1; x1 += ks2 + 4u;
    x0 += x1; x1 = rotl32(x1, 13); x1 ^= x0;
    x0 += x1; x1 = rotl32(x1, 15); x1 ^= x0;
    x0 += x1; x1 = rotl32(x1, 26); x1 ^= x0;
    x0 += x1; x1 = rotl32(x1,  6); x1 ^= x0;
    x0 += ks2; x1 += ks0 + 5u;
    o0 = x0; o1 = x1;
}

__device__ __forceinline__ int vbucket(float c) {
    float t = __fmul_rn(c, 4096.0f);
    int bk = (int)t;
    if (bk > 4095) bk = 4095;
    if (bk < 0) bk = 0;
    return bk;
}

// ---------------- K0a: zero scratch ----------------
__global__ void k_zero() {
    size_t n = (size_t)BB * 256 + 3ull * BB * NBUK;
    for (size_t i = blockIdx.x * (size_t)blockDim.x + threadIdx.x; i < n;
         i += (size_t)gridDim.x * blockDim.x) {
        if (i < (size_t)BB * 256) (&g_hist256[0][0])[i] = 0;
        else {
            size_t j = i - (size_t)BB * 256;
            if (j < (size_t)BB * NBUK) (&g_histBG[0][0])[j] = 0;
            else if (j < 2ull * BB * NBUK) (&g_histF[0][0])[j - (size_t)BB * NBUK] = 0;
            else (&g_histG[0][0])[j - 2ull * BB * NBUK] = 0;
        }
    }
    int t = blockIdx.x * blockDim.x + threadIdx.x;
    if (t < BB) { g_cntBG[t] = 0; g_cntF[t] = 0; g_cntG[t] = 0; }
}

// ---------------- K0b: per-batch keys + n_bg (threefry_partitionable) ----------------
__global__ void k_keys() {
    int b = threadIdx.x;
    if (b >= BB) return;
    // split(key(42), 128) partitionable: key_b = (o0, o1) of tf((0,42), (0, b))
    u32 a0, a1;
    tf2x32(0u, 42u, 0u, (u32)b, a0, a1);
    // split(key_b, 3): subkey_t = (o0, o1) of tf(key_b, (0, t))
    u32 kf0, kf1, kb0, kb1, kz0, kz1;
    tf2x32(a0, a1, 0u, 0u, kf0, kf1);
    tf2x32(a0, a1, 0u, 1u, kb0, kb1);
    tf2x32(a0, a1, 0u, 2u, kz0, kz1);
    g_kf[b] = make_uint2(kf0, kf1);
    g_kb[b] = make_uint2(kb0, kb1);
    // z = uniform(kz, (), 0.3, 0.7): bits = o0 ^ o1 of tf(kz, (0,0))
    u32 z0, z1;
    tf2x32(kz0, kz1, 0u, 0u, z0, z1);
    u32 zb = z0 ^ z1;
    float f = __fsub_rn(__uint_as_float((zb >> 9) | 0x3f800000u), 1.0f);
    float z = fmaxf(0.3f, __fadd_rn(__fmul_rn(f, __fsub_rn(0.7f, 0.3f)), 0.3f));
    g_nbg[b] = (int)ceilf(__fmul_rn(z, 262144.0f));
}

// ---------------- K1: per-batch hist256 + bg value histogram ----------------
__global__ void k_hist(const float* __restrict__ x) {
    __shared__ u32 s256[256];
    __shared__ u32 sBG[NBUK];
    int b = blockIdx.y;
    size_t base = (size_t)b * HWL;
    for (int i = threadIdx.x; i < 256; i += blockDim.x) s256[i] = 0;
    for (int i = threadIdx.x; i < NBUK; i += blockDim.x) sBG[i] = 0;
    __syncthreads();
    for (int i = blockIdx.x * blockDim.x + threadIdx.x; i < HWL; i += gridDim.x * blockDim.x) {
        float c = x[base + i];
        int v = (int)floorf(__fmul_rn(c, 255.0f));
        if (v < 0) v = 0; if (v > 255) v = 255;
        atomicAdd(&s256[v], 1u);
        atomicAdd(&sBG[vbucket(c)], 1u);
    }
    __syncthreads();
    for (int i = threadIdx.x; i < 256; i += blockDim.x)
        if (s256[i]) atomicAdd(&g_hist256[b][i], s256[i]);
    for (int i = threadIdx.x; i < NBUK; i += blockDim.x)
        if (sBG[i]) atomicAdd(&g_histBG[b][i], sBG[i]);
}

// ---------------- K2: Otsu (f32 emulation) + bg bucket scan ----------------
__global__ void k_scan1() {
    __shared__ u32 sh256[256];
    __shared__ u32 shBG[NBUK];
    int b = blockIdx.x;
    for (int i = threadIdx.x; i < 256; i += blockDim.x) sh256[i] = g_hist256[b][i];
    for (int i = threadIdx.x; i < NBUK; i += blockDim.x) shBG[i] = g_histBG[b][i];
    __syncthreads();
    if (threadIdx.x == 0) {
        const float total = 262144.0f;
        float mT = 0.0f;
        for (int t = 0; t < 256; t++)
            mT = __fadd_rn(mT, __fmul_rn((float)sh256[t], (float)t));
        float w = 0.0f, m = 0.0f;
        float best = -1.0f; int arg = 0;
        for (int t = 0; t < 256; t++) {
            w = __fadd_rn(w, (float)sh256[t]);
            m = __fadd_rn(m, __fmul_rn((float)sh256[t], (float)t));
            float denom = __fmul_rn(w, __fsub_rn(total, w));
            float sig = 0.0f;
            if (denom > 0.0f) {
                float num = __fsub_rn(__fmul_rn(mT, w), __fmul_rn(total, m));
                sig = __fdiv_rn(__fmul_rn(num, num),
                                __fmul_rn(__fmul_rn(denom, total), total));
            }
            if (sig > best) { best = sig; arg = t; }
        }
        float th = (float)arg;
        if (th == 0.0f) th = 1.0f;
        if (th == 255.0f) th = 254.0f;
        g_th[b] = th;
        int n = g_nbg[b];
        unsigned cum = 0; int c = 0;
        for (c = 0; c < NBUK; c++) {
            cum += shBG[c];
            if ((int)cum >= n) break;
        }
        g_cbg[b] = c;
        g_rbg[b] = n - (int)(cum - shBG[c]);
    }
}

// ---------------- K3: horizontal erosion + collect bg cutoff-bucket keys ----------------
__global__ void k_erodeH(const float* __restrict__ x) {
    __shared__ unsigned char s[WW];
    int r = blockIdx.x, b = blockIdx.y;
    int j = threadIdx.x;
    size_t idx = (size_t)b * HWL + (size_t)r * WW + j;
    float c = x[idx];
    float c255 = floorf(__fmul_rn(c, 255.0f));
    s[j] = (c255 > g_th[b]) ? 1 : 0;
    if (vbucket(c) == g_cbg[b]) {
        u32 pos = atomicAdd(&g_cntBG[b], 1u);
        int i = r * WW + j;
        if (pos < CAP) g_bufBG[b][pos] = (((u64)__float_as_uint(c)) << 18) | (u32)i;
    }
    __syncthreads();
    int lo = j - 5; if (lo < 0) lo = 0;
    int hi = j + 5; if (hi > WW - 1) hi = WW - 1;
    unsigned char v = 1;
    for (int t = lo; t <= hi; t++) v &= s[t];
    g_tmpH[idx] = v;
}

// ---------------- K4: vertical erosion ----------------
__global__ void k_erodeV() {
    __shared__ unsigned char s[74 * 256];
    int b = blockIdx.z, chunk = blockIdx.y, jb = blockIdx.x;
    int j = jb * 256 + threadIdx.x;
    int cs = chunk * 64;
    int lo = cs - 5; if (lo < 0) lo = 0;
    int hi = cs + 63 + 5; if (hi > HH - 1) hi = HH - 1;
    size_t base = (size_t)b * HWL;
    for (int t = lo; t <= hi; t++)
        s[(t - lo) * 256 + threadIdx.x] = g_tmpH[base + (size_t)t * WW + j];
    __syncthreads();
    for (int i = cs; i < cs + 64; i++) {
        int wl = i - 5; if (wl < 0) wl = 0;
        int wh = i + 5; if (wh > HH - 1) wh = HH - 1;
        unsigned char v = 1;
        for (int t = wl; t <= wh; t++) v &= s[(t - lo) * 256 + threadIdx.x];
        g_erod[base + (size_t)i * WW + j] = v;
    }
}

// ---------------- K5: exact n_bg-th smallest key ----------------
__global__ void k_selBG() {
    __shared__ u64 s[CAP];
    int b = blockIdx.x;
    int n = min(g_cntBG[b], (u32)CAP);
    int r = g_rbg[b];
    for (int i = threadIdx.x; i < n; i += blockDim.x) s[i] = g_bufBG[b][i];
    __syncthreads();
    for (int i = threadIdx.x; i < n; i += blockDim.x) {
        u64 e = s[i];
        int less = 0;
        for (int j = 0; j < n; j++) less += (s[j] < e);
        if (less == r - 1) g_KbgSel[b] = e;
    }
}

// ---------------- K6: threefry bits (partitionable) + elig flags + score hists ----------------
__global__ void k_histScores(const float* __restrict__ x) {
    __shared__ u32 sF[NBUK];
    __shared__ u32 sG[NBUK];
    int b = blockIdx.y;
    for (int i = threadIdx.x; i < NBUK; i += blockDim.x) { sF[i] = 0; sG[i] = 0; }
    __syncthreads();
    size_t base = (size_t)b * HWL;
    uint2 kf = g_kf[b], kb = g_kb[b];
    u64 Ksel = g_KbgSel[b];
    for (int i = blockIdx.x * blockDim.x + threadIdx.x; i < HWL; i += gridDim.x * blockDim.x) {
        unsigned char fe = g_erod[base + i];
        float c = x[base + i];
        u64 uk = (((u64)__float_as_uint(c)) << 18) | (u32)i;
        unsigned char ge = (uk <= Ksel) ? 1 : 0;
        // fg bits: only when some lane in warp is eligible (typically none)
        unsigned vote = __ballot_sync(0xFFFFFFFFu, fe != 0);
        if (vote) {
            u32 o0, o1;
            tf2x32(kf.x, kf.y, 0u, (u32)i, o0, o1);
            u32 fb = o0 ^ o1;
            if (fe) { g_fbits[base + i] = fb; atomicAdd(&sF[fb >> 20], 1u); }
        }
        // bg bits: compute unconditionally (eligible ~50% scattered => warp-dense anyway)
        {
            u32 o0, o1;
            tf2x32(kb.x, kb.y, 0u, (u32)i, o0, o1);
            u32 gb = o0 ^ o1;
            if (ge) { g_bbits[base + i] = gb; atomicAdd(&sG[gb >> 20], 1u); }
        }
        g_tmpH[base + i] = fe | (ge << 1);
    }
    __syncthreads();
    for (int i = threadIdx.x; i < NBUK; i += blockDim.x) {
        if (sF[i]) atomicAdd(&g_histF[b][i], sF[i]);
        if (sG[i]) atomicAdd(&g_histG[b][i], sG[i]);
    }
}

// ---------------- K7: top-1000 cutoff scan ----------------
__global__ void k_scan2() {
    __shared__ u32 shF[NBUK];
    __shared__ u32 shG[NBUK];
    int b = blockIdx.x;
    for (int i = threadIdx.x; i < NBUK; i += blockDim.x) {
        shF[i] = g_histF[b][i];
        shG[i] = g_histG[b][i];
    }
    __syncthreads();
    if (threadIdx.x == 0) {
        unsigned cum = 0; int cf = -1, rf = 0;
        for (int c = NBUK - 1; c >= 0; c--) {
            cum += shF[c];
            if (cum >= NSEEDS) { cf = c; rf = NSEEDS - (int)(cum - shF[c]); break; }
        }
        g_cF[b] = cf; g_rF[b] = rf;
        cum = 0; int cg = -1, rg = 0;
        for (int c = NBUK - 1; c >= 0; c--) {
            cum += shG[c];
            if (cum >= NSEEDS) { cg = c; rg = NSEEDS - (int)(cum - shG[c]); break; }
        }
        g_cG[b] = cg; g_rG[b] = rg;
    }
}

// ---------------- K8: mark definite selections, collect cutoff-bucket candidates ----------------
__global__ void k_mark() {
    int b = blockIdx.y;
    size_t base = (size_t)b * HWL;
    int cF = g_cF[b], cG = g_cG[b];
    for (int i = blockIdx.x * blockDim.x + threadIdx.x; i < HWL; i += gridDim.x * blockDim.x) {
        unsigned char fl = g_tmpH[base + i];
        unsigned char m = 0;
        if (fl & 1) {
            u32 fb = g_fbits[base + i];
            int bu = (int)(fb >> 20);
            if (bu > cF) m |= 1;
            else if (bu == cF) {
                u32 pos = atomicAdd(&g_cntF[b], 1u);
                if (pos < CAP)
                    g_bufF[b][pos] = (((u64)(fb >> 9)) << 18) | (u32)(0x3FFFF - i);
            }
        }
        if (fl & 2) {
            u32 gb = g_bbits[base + i];
            int bu = (int)(gb >> 20);
            if (bu > cG) m |= 2;
            else if (bu == cG) {
                u32 pos = atomicAdd(&g_cntG[b], 1u);
                if (pos < CAP)
                    g_bufG[b][pos] = (((u64)(gb >> 9)) << 18) | (u32)(0x3FFFF - i);
            }
        }
        g_mask[base + i] = m;
    }
}

// ---------------- K9: finish selection within cutoff buckets ----------------
__global__ void k_finishSel() {
    __shared__ u64 s[CAP];
    int bi = blockIdx.x;
    int b = bi >> 1, which = bi & 1;
    int cf = which ? g_cG[b] : g_cF[b];
    int r = which ? g_rG[b] : g_rF[b];
    u32 cnt = which ? g_cntG[b] : g_cntF[b];
    int n = (cf >= 0) ? (int)min(cnt, (u32)CAP) : 0;
    const u64* buf = which ? g_bufG[b] : g_bufF[b];
    for (int i = threadIdx.x; i < n; i += blockDim.x) s[i] = buf[i];
    __syncthreads();
    unsigned bit = which ? 2u : 1u;
    size_t base = (size_t)b * HWL;
    for (int i = threadIdx.x; i < n; i += blockDim.x) {
        u64 e = s[i];
        int g = 0;
        for (int j = 0; j < n; j++) g += (s[j] > e);
        if (g < r) {
            int idx = 0x3FFFF - (int)(e & 0x3FFFFu);
            u32* wp = (u32*)(g_mask + base + (size_t)(idx & ~3));
            atomicOr(wp, bit << (8 * (idx & 3)));
        }
    }
}

// ---------------- K10: 3x3 dilation + overlap removal + float labels ----------------
__global__ void k_out(float* __restrict__ out) {
    int b = blockIdx.y;
    int i = blockIdx.x * blockDim.x + threadIdx.x;
    if (i >= HWL) return;
    int r = i >> 9, c = i & 511;
    const unsigned char* m = g_mask + (size_t)b * HWL;
    unsigned a = 0;
#pragma unroll
    for (int dr = -1; dr <= 1; dr++) {
        int rr = r + dr;
        if (rr < 0 || rr > HH - 1) continue;
#pragma unroll
        for (int dc = -1; dc <= 1; dc++) {
            int cc = c + dc;
            if (cc < 0 || cc > WW - 1) continue;
            a |= m[(size_t)rr * WW + cc];
        }
    }
    int fg = a & 1, bg = (a >> 1) & 1;
    float v = -255.0f;
    if (fg && bg) v = -255.0f;
    else if (fg) v = 1.0f;
    else if (bg) v = 0.0f;
    out[(size_t)b * HWL + i] = v;
}

// ---------------- launch ----------------
extern "C" void kernel_launch(void* const* d_in, const int* in_sizes, int n_in,
                              void* d_out, int out_size) {
    const float* x = (const float*)d_in[0];
    float* out = (float*)d_out;
    (void)in_sizes; (void)n_in; (void)out_size;

    k_zero<<<2048, 256>>>();
    k_keys<<<1, 128>>>();
    k_hist<<<dim3(16, BB), 256>>>(x);
    k_scan1<<<BB, 128>>>();
    k_erodeH<<<dim3(HH, BB), WW>>>(x);
    k_erodeV<<<dim3(2, 8, BB), 256>>>();
    k_selBG<<<BB, 256>>>();
    k_histScores<<<dim3(64, BB), 256>>>(x);
    k_scan2<<<BB, 128>>>();
    k_mark<<<dim3(16, BB), 256>>>();
    k_finishSel<<<2 * BB, 256>>>();
    k_out<<<dim3(HWL / 256, BB), 256>>>(out);
}